// round 12
// baseline (speedup 1.0000x reference)
#include <cuda_runtime.h>
#include <cuda_bf16.h>
#include <cstdint>

// Problem constants
#define BATCH 64
#define SEQ   197
#define DIM   768
#define HEADS 12
#define HD    64
#define M_TOT (BATCH * SEQ)      // 12608
#define QKV_N (3 * DIM)          // 2304
#define KDIM  768

// Scratch (bf16 end-to-end between GEMMs)
__device__ __nv_bfloat16 g_qkvb[(size_t)M_TOT * QKV_N];
__device__ __nv_bfloat16 g_xb[(size_t)M_TOT * DIM];
__device__ __nv_bfloat16 g_wqb[(size_t)QKV_N * KDIM];
__device__ __nv_bfloat16 g_wpb[(size_t)DIM * KDIM];
__device__ __nv_bfloat16 g_attb[(size_t)M_TOT * DIM];

__device__ __forceinline__ uint32_t smem_u32(const void* p) {
    uint32_t a;
    asm("{ .reg .u64 t; cvta.to.shared.u64 t, %1; cvt.u32.u64 %0, t; }" : "=r"(a) : "l"(p));
    return a;
}

__device__ __forceinline__ void mma_bf16(float* c, const uint32_t* a,
                                         uint32_t b0, uint32_t b1) {
    asm volatile(
        "mma.sync.aligned.m16n8k16.row.col.f32.bf16.bf16.f32 "
        "{%0,%1,%2,%3}, {%4,%5,%6,%7}, {%8,%9}, {%0,%1,%2,%3};"
        : "+f"(c[0]), "+f"(c[1]), "+f"(c[2]), "+f"(c[3])
        : "r"(a[0]), "r"(a[1]), "r"(a[2]), "r"(a[3]), "r"(b0), "r"(b1));
}

#define LDSM4(r, addr) \
    asm volatile("ldmatrix.sync.aligned.m8n8.x4.shared.b16 {%0,%1,%2,%3}, [%4];" \
                 : "=r"((r)[0]), "=r"((r)[1]), "=r"((r)[2]), "=r"((r)[3]) : "r"(addr))
#define LDSM4T(r, addr) \
    asm volatile("ldmatrix.sync.aligned.m8n8.x4.trans.shared.b16 {%0,%1,%2,%3}, [%4];" \
                 : "=r"((r)[0]), "=r"((r)[1]), "=r"((r)[2]), "=r"((r)[3]) : "r"(addr))

__device__ __forceinline__ uint32_t pack_bf16(float lo, float hi) {
    __nv_bfloat162 v = __floats2bfloat162_rn(lo, hi);
    return *(uint32_t*)&v;
}

// ---------------------------------------------------------------------------
// fused fp32 -> bf16 conversion for x, w_qkv, w_proj (single launch)
// ---------------------------------------------------------------------------
#define N4_X   ((M_TOT * DIM) / 4)
#define N4_WQ  ((QKV_N * KDIM) / 4)
#define N4_WP  ((DIM * KDIM) / 4)
#define N4_ALL (N4_X + N4_WQ + N4_WP)

__global__ void cvt_all(const float* __restrict__ x,
                        const float* __restrict__ wq,
                        const float* __restrict__ wp,
                        __nv_bfloat16* __restrict__ xb,
                        __nv_bfloat16* __restrict__ wqb,
                        __nv_bfloat16* __restrict__ wpb)
{
    int i = blockIdx.x * blockDim.x + threadIdx.x;
    const float* in;
    __nv_bfloat16* out;
    if (i < N4_X) { in = x; out = xb; }
    else if (i < N4_X + N4_WQ) { i -= N4_X; in = wq; out = wqb; }
    else if (i < N4_ALL) { i -= N4_X + N4_WQ; in = wp; out = wpb; }
    else return;
    const float4 v = ((const float4*)in)[i];
    ((__nv_bfloat162*)out)[2 * i]     = __floats2bfloat162_rn(v.x, v.y);
    ((__nv_bfloat162*)out)[2 * i + 1] = __floats2bfloat162_rn(v.z, v.w);
}

// ---------------------------------------------------------------------------
// bf16 mma.sync GEMM (NT), CTA 128x128 — R9/R11 version (GEMM1)
// ---------------------------------------------------------------------------
#define MT 128
#define NTL 128
#define BKC 64
#define BNKT (KDIM / BKC)          // 12
#define BROWB 144
#define BSTG (256 * BROWB)         // 36864 B per stage
#define NSTG 3
#define BGEMM_SMEM (NSTG * BSTG)   // 110592 B

template <bool EPI, typename OutT>
__global__ __launch_bounds__(256, 2)
void bf16_gemm(const __nv_bfloat16* __restrict__ A,
               const __nv_bfloat16* __restrict__ B,
               OutT* __restrict__ C, int M, int Ng,
               const float* __restrict__ bias, const float* __restrict__ res)
{
    extern __shared__ char smc[];
    const uint32_t sb = smem_u32(smc);

    const int tid = threadIdx.x;
    const int bm = blockIdx.x * MT;
    const int bn = blockIdx.y * NTL;

    const int w = tid >> 5, lane = tid & 31;
    const int wm = (w & 1) * 64;
    const int wn = (w >> 1) * 32;
    const int g = lane >> 2;
    const int tk = lane & 3;

    float acc[4][4][4];
#pragma unroll
    for (int i = 0; i < 4; i++)
#pragma unroll
        for (int j = 0; j < 4; j++)
#pragma unroll
            for (int q = 0; q < 4; q++) acc[i][j][q] = 0.f;

    auto load_stage = [&](int s, int kt) {
        const uint32_t Asm = sb + s * BSTG;
        const uint32_t Bsm = Asm + 128 * BROWB;
        const int k0 = kt * BKC;
#pragma unroll
        for (int c4 = 0; c4 < 4; c4++) {
            const int c = tid + c4 * 256;
            const int row = c >> 3, kq = c & 7;
            const int m = bm + row;
            const __nv_bfloat16* src =
                A + (size_t)(m < M ? m : M - 1) * KDIM + k0 + kq * 8;
            const uint32_t dst = Asm + row * BROWB + kq * 16;
            const int sz = (m < M) ? 16 : 0;
            asm volatile("cp.async.cg.shared.global [%0], [%1], 16, %2;"
                         :: "r"(dst), "l"(src), "r"(sz) : "memory");
        }
#pragma unroll
        for (int c4 = 0; c4 < 4; c4++) {
            const int c = tid + c4 * 256;
            const int row = c >> 3, kq = c & 7;
            const __nv_bfloat16* src =
                B + (size_t)(bn + row) * KDIM + k0 + kq * 8;
            const uint32_t dst = Bsm + row * BROWB + kq * 16;
            asm volatile("cp.async.cg.shared.global [%0], [%1], 16, 16;"
                         :: "r"(dst), "l"(src) : "memory");
        }
    };

#pragma unroll
    for (int s = 0; s < NSTG - 1; s++) {
        load_stage(s, s);
        asm volatile("cp.async.commit_group;" ::: "memory");
    }

    int sc_ = 0;
    for (int kt = 0; kt < BNKT; kt++) {
        asm volatile("cp.async.wait_group %0;" :: "n"(NSTG - 2) : "memory");
        __syncthreads();
        if (kt + NSTG - 1 < BNKT) {
            int ns = sc_ + 2; if (ns >= NSTG) ns -= NSTG;
            load_stage(ns, kt + NSTG - 1);
        }
        asm volatile("cp.async.commit_group;" ::: "memory");

        const uint32_t Asm = sb + sc_ * BSTG;
        const uint32_t Bsm = Asm + 128 * BROWB;

#pragma unroll
        for (int ks = 0; ks < 4; ks++) {
            const int kb = ks * 32;
            uint32_t af[4][4], bf[4][2];
#pragma unroll
            for (int mt = 0; mt < 4; mt++) {
                const uint32_t a =
                    Asm + (wm + mt * 16 + (lane & 15)) * BROWB + (lane >> 4) * 16 + kb;
                LDSM4(af[mt], a);
            }
#pragma unroll
            for (int p = 0; p < 2; p++) {
                const int t = lane >> 3;
                const int nr = wn + (2 * p + (t >> 1)) * 8 + (lane & 7);
                const uint32_t a = Bsm + nr * BROWB + (t & 1) * 16 + kb;
                uint32_t r[4];
                LDSM4(r, a);
                bf[2 * p][0] = r[0]; bf[2 * p][1] = r[1];
                bf[2 * p + 1][0] = r[2]; bf[2 * p + 1][1] = r[3];
            }
#pragma unroll
            for (int mt = 0; mt < 4; mt++)
#pragma unroll
                for (int nt = 0; nt < 4; nt++)
                    mma_bf16(acc[mt][nt], af[mt], bf[nt][0], bf[nt][1]);
        }
        if (++sc_ >= NSTG) sc_ = 0;
    }

#pragma unroll
    for (int mt = 0; mt < 4; mt++) {
#pragma unroll
        for (int half = 0; half < 2; half++) {
            const int m = bm + wm + mt * 16 + g + half * 8;
            if (m < M) {
#pragma unroll
                for (int nt = 0; nt < 4; nt++) {
                    const int n = bn + wn + nt * 8 + 2 * tk;
                    float vx = acc[mt][nt][half * 2 + 0];
                    float vy = acc[mt][nt][half * 2 + 1];
                    if (EPI) {
                        const float2 bz = *(const float2*)&bias[n];
                        const float2 rz = *(const float2*)&res[(size_t)m * Ng + n];
                        vx += bz.x + rz.x;
                        vy += bz.y + rz.y;
                    }
                    if (sizeof(OutT) == 2) {
                        *(__nv_bfloat162*)&C[(size_t)m * Ng + n] =
                            __floats2bfloat162_rn(vx, vy);
                    } else {
                        float2 v; v.x = vx; v.y = vy;
                        *(float2*)&C[(size_t)m * Ng + n] = v;
                    }
                }
            }
        }
    }
}

// ---------------------------------------------------------------------------
// bf16 mma.sync GEMM (NT), CTA 64x128 (GEMM3): 197x6 = 1182 CTAs = 3.99 waves
// 8 warps (2x4), warp tile 32x32. Fused bias + residual epilogue, fp32 out.
// ---------------------------------------------------------------------------
#define M64STG (192 * BROWB)           // 27648 B per stage (A 64 + B 128 rows)
#define M64_SMEM (NSTG * M64STG)       // 82944 B (x2 CTAs = 165888 <= 228K)

__global__ __launch_bounds__(256, 2)
void bf16_gemm_m64(const __nv_bfloat16* __restrict__ A,
                   const __nv_bfloat16* __restrict__ B,
                   float* __restrict__ C, int M, int Ng,
                   const float* __restrict__ bias, const float* __restrict__ res)
{
    extern __shared__ char smc[];
    const uint32_t sb = smem_u32(smc);

    const int tid = threadIdx.x;
    const int bm = blockIdx.x * 64;
    const int bn = blockIdx.y * NTL;

    const int w = tid >> 5, lane = tid & 31;
    const int wm = (w & 1) * 32;
    const int wn = (w >> 1) * 32;
    const int g = lane >> 2;
    const int tk = lane & 3;

    float acc[2][4][4];
#pragma unroll
    for (int i = 0; i < 2; i++)
#pragma unroll
        for (int j = 0; j < 4; j++)
#pragma unroll
            for (int q = 0; q < 4; q++) acc[i][j][q] = 0.f;

    auto load_stage = [&](int s, int kt) {
        const uint32_t Asm = sb + s * M64STG;
        const uint32_t Bsm = Asm + 64 * BROWB;
        const int k0 = kt * BKC;
#pragma unroll
        for (int c4 = 0; c4 < 2; c4++) {        // A: 512 chunks
            const int c = tid + c4 * 256;
            const int row = c >> 3, kq = c & 7;
            const int m = bm + row;
            const __nv_bfloat16* src =
                A + (size_t)(m < M ? m : M - 1) * KDIM + k0 + kq * 8;
            const uint32_t dst = Asm + row * BROWB + kq * 16;
            const int sz = (m < M) ? 16 : 0;
            asm volatile("cp.async.cg.shared.global [%0], [%1], 16, %2;"
                         :: "r"(dst), "l"(src), "r"(sz) : "memory");
        }
#pragma unroll
        for (int c4 = 0; c4 < 4; c4++) {        // B: 1024 chunks
            const int c = tid + c4 * 256;
            const int row = c >> 3, kq = c & 7;
            const __nv_bfloat16* src =
                B + (size_t)(bn + row) * KDIM + k0 + kq * 8;
            const uint32_t dst = Bsm + row * BROWB + kq * 16;
            asm volatile("cp.async.cg.shared.global [%0], [%1], 16, 16;"
                         :: "r"(dst), "l"(src) : "memory");
        }
    };

#pragma unroll
    for (int s = 0; s < NSTG - 1; s++) {
        load_stage(s, s);
        asm volatile("cp.async.commit_group;" ::: "memory");
    }

    int sc_ = 0;
    for (int kt = 0; kt < BNKT; kt++) {
        asm volatile("cp.async.wait_group %0;" :: "n"(NSTG - 2) : "memory");
        __syncthreads();
        if (kt + NSTG - 1 < BNKT) {
            int ns = sc_ + 2; if (ns >= NSTG) ns -= NSTG;
            load_stage(ns, kt + NSTG - 1);
        }
        asm volatile("cp.async.commit_group;" ::: "memory");

        const uint32_t Asm = sb + sc_ * M64STG;
        const uint32_t Bsm = Asm + 64 * BROWB;

#pragma unroll
        for (int ks = 0; ks < 4; ks++) {
            const int kb = ks * 32;
            uint32_t af[2][4], bf[4][2];
#pragma unroll
            for (int mt = 0; mt < 2; mt++) {
                const uint32_t a =
                    Asm + (wm + mt * 16 + (lane & 15)) * BROWB + (lane >> 4) * 16 + kb;
                LDSM4(af[mt], a);
            }
#pragma unroll
            for (int p = 0; p < 2; p++) {
                const int t = lane >> 3;
                const int nr = wn + (2 * p + (t >> 1)) * 8 + (lane & 7);
                const uint32_t a = Bsm + nr * BROWB + (t & 1) * 16 + kb;
                uint32_t r[4];
                LDSM4(r, a);
                bf[2 * p][0] = r[0]; bf[2 * p][1] = r[1];
                bf[2 * p + 1][0] = r[2]; bf[2 * p + 1][1] = r[3];
            }
#pragma unroll
            for (int mt = 0; mt < 2; mt++)
#pragma unroll
                for (int nt = 0; nt < 4; nt++)
                    mma_bf16(acc[mt][nt], af[mt], bf[nt][0], bf[nt][1]);
        }
        if (++sc_ >= NSTG) sc_ = 0;
    }

    // epilogue (fp32, bias + residual)
#pragma unroll
    for (int mt = 0; mt < 2; mt++) {
#pragma unroll
        for (int half = 0; half < 2; half++) {
            const int m = bm + wm + mt * 16 + g + half * 8;
            if (m < M) {
#pragma unroll
                for (int nt = 0; nt < 4; nt++) {
                    const int n = bn + wn + nt * 8 + 2 * tk;
                    float vx = acc[mt][nt][half * 2 + 0];
                    float vy = acc[mt][nt][half * 2 + 1];
                    const float2 bz = *(const float2*)&bias[n];
                    const float2 rz = *(const float2*)&res[(size_t)m * Ng + n];
                    vx += bz.x + rz.x;
                    vy += bz.y + rz.y;
                    float2 v; v.x = vx; v.y = vy;
                    *(float2*)&C[(size_t)m * Ng + n] = v;
                }
            }
        }
    }
}

// ---------------------------------------------------------------------------
// bf16 mma.sync attention, flash-style 2-chunk online softmax (R11, passed)
// ---------------------------------------------------------------------------
#define AJP 208
#define AROWB2 144
#define ATT_SMEM (3 * AJP * AROWB2)   // 89856 B

__global__ __launch_bounds__(256, 2)
void attn_bf16(const __nv_bfloat16* __restrict__ qkv,
               const float* __restrict__ scale,
               __nv_bfloat16* __restrict__ attout)
{
    const int bh = blockIdx.x;
    const int b = bh / HEADS;
    const int h = bh % HEADS;
    const float sc = scale[h];

    extern __shared__ char smc[];
    const uint32_t sb = smem_u32(smc);
    const uint32_t Qs = sb;
    const uint32_t Ks = sb + AJP * AROWB2;
    const uint32_t Vs = sb + 2 * AJP * AROWB2;

    const int tid = threadIdx.x;
    const __nv_bfloat16* base = qkv + (size_t)b * SEQ * QKV_N + h * HD;

    for (int c = tid; c < 3 * AJP * 8; c += 256) {
        const int t = c / (AJP * 8);
        const int rc = c % (AJP * 8);
        const int row = rc >> 3, ch = rc & 7;
        const __nv_bfloat16* src =
            base + (size_t)(row < SEQ ? row : SEQ - 1) * QKV_N + t * DIM + ch * 8;
        const uint32_t dst = sb + t * (AJP * AROWB2) + row * AROWB2 + ch * 16;
        const int sz = (row < SEQ) ? 16 : 0;
        asm volatile("cp.async.cg.shared.global [%0], [%1], 16, %2;"
                     :: "r"(dst), "l"(src), "r"(sz) : "memory");
    }
    asm volatile("cp.async.commit_group;" ::: "memory");
    asm volatile("cp.async.wait_group 0;" ::: "memory");
    __syncthreads();

    const int w = tid >> 5;
    const int lane = tid & 31;
    const int g = lane >> 2;
    const int tk = lane & 3;

    for (int rb = 0; rb < 2; rb++) {
        const int rowbase = rb * 128 + w * 16;
        if (rowbase >= SEQ) continue;
        const int rlo = rowbase + g;
        const int rhi = rlo + 8;

        uint32_t qa[4][4];
#pragma unroll
        for (int ks = 0; ks < 4; ks++)
            LDSM4(qa[ks], Qs + (rowbase + (lane & 15)) * AROWB2
                             + (lane >> 4) * 16 + ks * 32);

        float run_mlo = -1e30f, run_mhi = -1e30f;
        float slo = 0.f, shi = 0.f;
        float O[8][4];
#pragma unroll
        for (int dt = 0; dt < 8; dt++)
            O[dt][0] = O[dt][1] = O[dt][2] = O[dt][3] = 0.f;

#pragma unroll
        for (int c = 0; c < 2; c++) {
            const int p0 = (c == 0) ? 0 : 7;
            const int p1 = (c == 0) ? 7 : 13;
            const int NP = p1 - p0;

            float S[7][2][4];
#pragma unroll
            for (int l = 0; l < 7; l++) {
                if (l >= NP) break;
                const int np = p0 + l;
                S[l][0][0] = S[l][0][1] = S[l][0][2] = S[l][0][3] = 0.f;
                S[l][1][0] = S[l][1][1] = S[l][1][2] = S[l][1][3] = 0.f;
#pragma unroll
                for (int ks = 0; ks < 4; ks++) {
                    uint32_t r[4];
                    LDSM4(r, Ks + (np * 16 + (lane & 15)) * AROWB2
                                + (lane >> 4) * 16 + ks * 32);
                    mma_bf16(S[l][0], qa[ks], r[0], r[2]);
                    mma_bf16(S[l][1], qa[ks], r[1], r[3]);
                }
            }

#pragma unroll
            for (int l = 0; l < 7; l++) {
                if (l >= NP) break;
#pragma unroll
                for (int hf = 0; hf < 2; hf++) {
                    const int j0 = (2 * (p0 + l) + hf) * 8 + 2 * tk;
                    const int j1 = j0 + 1;
                    S[l][hf][0] = (j0 == rlo || j0 >= SEQ) ? -1e30f : S[l][hf][0] * sc;
                    S[l][hf][1] = (j1 == rlo || j1 >= SEQ) ? -1e30f : S[l][hf][1] * sc;
                    S[l][hf][2] = (j0 == rhi || j0 >= SEQ) ? -1e30f : S[l][hf][2] * sc;
                    S[l][hf][3] = (j1 == rhi || j1 >= SEQ) ? -1e30f : S[l][hf][3] * sc;
                }
            }

            float cmlo = -1e30f, cmhi = -1e30f;
#pragma unroll
            for (int l = 0; l < 7; l++) {
                if (l >= NP) break;
#pragma unroll
                for (int hf = 0; hf < 2; hf++) {
                    cmlo = fmaxf(cmlo, fmaxf(S[l][hf][0], S[l][hf][1]));
                    cmhi = fmaxf(cmhi, fmaxf(S[l][hf][2], S[l][hf][3]));
                }
            }
            cmlo = fmaxf(cmlo, __shfl_xor_sync(0xffffffffu, cmlo, 1));
            cmlo = fmaxf(cmlo, __shfl_xor_sync(0xffffffffu, cmlo, 2));
            cmhi = fmaxf(cmhi, __shfl_xor_sync(0xffffffffu, cmhi, 1));
            cmhi = fmaxf(cmhi, __shfl_xor_sync(0xffffffffu, cmhi, 2));

            const float nmlo = fmaxf(run_mlo, cmlo);
            const float nmhi = fmaxf(run_mhi, cmhi);
            const float rfl = __expf(run_mlo - nmlo);
            const float rfh = __expf(run_mhi - nmhi);
            run_mlo = nmlo; run_mhi = nmhi;
            slo *= rfl; shi *= rfh;
#pragma unroll
            for (int dt = 0; dt < 8; dt++) {
                O[dt][0] *= rfl; O[dt][1] *= rfl;
                O[dt][2] *= rfh; O[dt][3] *= rfh;
            }

#pragma unroll
            for (int l = 0; l < 7; l++) {
                if (l >= NP) break;
#pragma unroll
                for (int hf = 0; hf < 2; hf++) {
                    S[l][hf][0] = __expf(S[l][hf][0] - nmlo);
                    S[l][hf][1] = __expf(S[l][hf][1] - nmlo);
                    S[l][hf][2] = __expf(S[l][hf][2] - nmhi);
                    S[l][hf][3] = __expf(S[l][hf][3] - nmhi);
                    slo += S[l][hf][0] + S[l][hf][1];
                    shi += S[l][hf][2] + S[l][hf][3];
                }
            }

#pragma unroll
            for (int l = 0; l < 7; l++) {
                if (l >= NP) break;
                uint32_t pa[4];
                pa[0] = pack_bf16(S[l][0][0], S[l][0][1]);
                pa[1] = pack_bf16(S[l][0][2], S[l][0][3]);
                pa[2] = pack_bf16(S[l][1][0], S[l][1][1]);
                pa[3] = pack_bf16(S[l][1][2], S[l][1][3]);
#pragma unroll
                for (int dp = 0; dp < 4; dp++) {
                    uint32_t r[4];
                    LDSM4T(r, Vs + ((p0 + l) * 16 + (lane & 15)) * AROWB2
                                 + (lane >> 4) * 16 + dp * 32);
                    mma_bf16(O[2 * dp],     pa, r[0], r[1]);
                    mma_bf16(O[2 * dp + 1], pa, r[2], r[3]);
                }
            }
        }

        slo += __shfl_xor_sync(0xffffffffu, slo, 1);
        slo += __shfl_xor_sync(0xffffffffu, slo, 2);
        shi += __shfl_xor_sync(0xffffffffu, shi, 1);
        shi += __shfl_xor_sync(0xffffffffu, shi, 2);
        const float inv_lo = 1.f / slo;
        const float inv_hi = 1.f / shi;

        __nv_bfloat16* orow_lo = attout + (size_t)(b * SEQ + rlo) * DIM + h * HD;
        __nv_bfloat16* orow_hi = attout + (size_t)(b * SEQ + rhi) * DIM + h * HD;
#pragma unroll
        for (int dt = 0; dt < 8; dt++) {
            const int d = dt * 8 + 2 * tk;
            if (rlo < SEQ)
                *(__nv_bfloat162*)&orow_lo[d] =
                    __floats2bfloat162_rn(O[dt][0] * inv_lo, O[dt][1] * inv_lo);
            if (rhi < SEQ)
                *(__nv_bfloat162*)&orow_hi[d] =
                    __floats2bfloat162_rn(O[dt][2] * inv_hi, O[dt][3] * inv_hi);
        }
    }
}

// ---------------------------------------------------------------------------
extern "C" void kernel_launch(void* const* d_in, const int* in_sizes, int n_in,
                              void* d_out, int out_size)
{
    const float* x      = (const float*)d_in[0];
    const float* scale  = (const float*)d_in[1];
    const float* w_qkv  = (const float*)d_in[2];
    const float* w_proj = (const float*)d_in[3];
    const float* b_proj = (const float*)d_in[4];
    float* out = (float*)d_out;

    __nv_bfloat16* qkvb;  cudaGetSymbolAddress((void**)&qkvb, g_qkvb);
    __nv_bfloat16* xb;    cudaGetSymbolAddress((void**)&xb, g_xb);
    __nv_bfloat16* wqb;   cudaGetSymbolAddress((void**)&wqb, g_wqb);
    __nv_bfloat16* wpb;   cudaGetSymbolAddress((void**)&wpb, g_wpb);
    __nv_bfloat16* attb;  cudaGetSymbolAddress((void**)&attb, g_attb);

    cudaFuncSetAttribute((const void*)bf16_gemm<false, __nv_bfloat16>,
                         cudaFuncAttributeMaxDynamicSharedMemorySize, BGEMM_SMEM);
    cudaFuncSetAttribute((const void*)bf16_gemm_m64,
                         cudaFuncAttributeMaxDynamicSharedMemorySize, M64_SMEM);
    cudaFuncSetAttribute((const void*)attn_bf16,
                         cudaFuncAttributeMaxDynamicSharedMemorySize, ATT_SMEM);

    // 0) fused fp32 -> bf16 conversion
    cvt_all<<<(N4_ALL + 255) / 256, 256>>>(x, w_qkv, w_proj, xb, wqb, wpb);

    // 1) qkv = x @ w_qkv^T  (128x128 tiles)
    dim3 g1((M_TOT + MT - 1) / MT, QKV_N / NTL);
    bf16_gemm<false, __nv_bfloat16><<<g1, 256, BGEMM_SMEM>>>(
        xb, wqb, qkvb, M_TOT, QKV_N, nullptr, nullptr);

    // 2) attention (online-softmax, 2 CTAs/SM)
    attn_bf16<<<BATCH * HEADS, 256, ATT_SMEM>>>(qkvb, scale, attb);

    // 3) out = att @ w_proj^T + b_proj + x  (64x128 tiles: 1182 CTAs ~ 4 waves)
    dim3 g2(M_TOT / 64, DIM / NTL);
    bf16_gemm_m64<<<g2, 256, M64_SMEM>>>(attb, wpb, out, M_TOT, DIM, b_proj, x);
}

// round 13
// speedup vs baseline: 1.0462x; 1.0462x over previous
#include <cuda_runtime.h>
#include <cuda_bf16.h>
#include <cstdint>

// Problem constants
#define BATCH 64
#define SEQ   197
#define DIM   768
#define HEADS 12
#define HD    64
#define M_TOT (BATCH * SEQ)      // 12608
#define QKV_N (3 * DIM)          // 2304
#define KDIM  768

// Scratch (bf16 end-to-end between GEMMs)
__device__ __nv_bfloat16 g_qkvb[(size_t)M_TOT * QKV_N];
__device__ __nv_bfloat16 g_xb[(size_t)M_TOT * DIM];
__device__ __nv_bfloat16 g_wqb[(size_t)QKV_N * KDIM];
__device__ __nv_bfloat16 g_wpb[(size_t)DIM * KDIM];
__device__ __nv_bfloat16 g_attb[(size_t)M_TOT * DIM];

__device__ __forceinline__ uint32_t smem_u32(const void* p) {
    uint32_t a;
    asm("{ .reg .u64 t; cvta.to.shared.u64 t, %1; cvt.u32.u64 %0, t; }" : "=r"(a) : "l"(p));
    return a;
}

__device__ __forceinline__ void mma_bf16(float* c, const uint32_t* a,
                                         uint32_t b0, uint32_t b1) {
    asm volatile(
        "mma.sync.aligned.m16n8k16.row.col.f32.bf16.bf16.f32 "
        "{%0,%1,%2,%3}, {%4,%5,%6,%7}, {%8,%9}, {%0,%1,%2,%3};"
        : "+f"(c[0]), "+f"(c[1]), "+f"(c[2]), "+f"(c[3])
        : "r"(a[0]), "r"(a[1]), "r"(a[2]), "r"(a[3]), "r"(b0), "r"(b1));
}

#define LDSM4(r, addr) \
    asm volatile("ldmatrix.sync.aligned.m8n8.x4.shared.b16 {%0,%1,%2,%3}, [%4];" \
                 : "=r"((r)[0]), "=r"((r)[1]), "=r"((r)[2]), "=r"((r)[3]) : "r"(addr))
#define LDSM4T(r, addr) \
    asm volatile("ldmatrix.sync.aligned.m8n8.x4.trans.shared.b16 {%0,%1,%2,%3}, [%4];" \
                 : "=r"((r)[0]), "=r"((r)[1]), "=r"((r)[2]), "=r"((r)[3]) : "r"(addr))

__device__ __forceinline__ uint32_t pack_bf16(float lo, float hi) {
    __nv_bfloat162 v = __floats2bfloat162_rn(lo, hi);
    return *(uint32_t*)&v;
}

// ---------------------------------------------------------------------------
// fused fp32 -> bf16 conversion for x, w_qkv, w_proj (single launch)
// ---------------------------------------------------------------------------
#define N4_X   ((M_TOT * DIM) / 4)
#define N4_WQ  ((QKV_N * KDIM) / 4)
#define N4_WP  ((DIM * KDIM) / 4)
#define N4_ALL (N4_X + N4_WQ + N4_WP)

__global__ void cvt_all(const float* __restrict__ x,
                        const float* __restrict__ wq,
                        const float* __restrict__ wp,
                        __nv_bfloat16* __restrict__ xb,
                        __nv_bfloat16* __restrict__ wqb,
                        __nv_bfloat16* __restrict__ wpb)
{
    int i = blockIdx.x * blockDim.x + threadIdx.x;
    const float* in;
    __nv_bfloat16* out;
    if (i < N4_X) { in = x; out = xb; }
    else if (i < N4_X + N4_WQ) { i -= N4_X; in = wq; out = wqb; }
    else if (i < N4_ALL) { i -= N4_X + N4_WQ; in = wp; out = wpb; }
    else return;
    const float4 v = ((const float4*)in)[i];
    ((__nv_bfloat162*)out)[2 * i]     = __floats2bfloat162_rn(v.x, v.y);
    ((__nv_bfloat162*)out)[2 * i + 1] = __floats2bfloat162_rn(v.z, v.w);
}

// ---------------------------------------------------------------------------
// bf16 mma.sync GEMM (NT), CTA 128x128, warp 64x32, K-chunk 64, 3 stages.
// (R9/R11 version — best measured)
// ---------------------------------------------------------------------------
#define MT 128
#define NTL 128
#define BKC 64
#define BNKT (KDIM / BKC)          // 12
#define BROWB 144
#define BSTG (256 * BROWB)         // 36864 B per stage
#define NSTG 3
#define BGEMM_SMEM (NSTG * BSTG)   // 110592 B (x2 CTAs = 221184 <= 228K)

template <bool EPI, typename OutT>
__global__ __launch_bounds__(256, 2)
void bf16_gemm(const __nv_bfloat16* __restrict__ A,
               const __nv_bfloat16* __restrict__ B,
               OutT* __restrict__ C, int M, int Ng,
               const float* __restrict__ bias, const float* __restrict__ res)
{
    extern __shared__ char smc[];
    const uint32_t sb = smem_u32(smc);

    const int tid = threadIdx.x;
    const int bm = blockIdx.x * MT;
    const int bn = blockIdx.y * NTL;

    const int w = tid >> 5, lane = tid & 31;
    const int wm = (w & 1) * 64;
    const int wn = (w >> 1) * 32;
    const int g = lane >> 2;
    const int tk = lane & 3;

    float acc[4][4][4];
#pragma unroll
    for (int i = 0; i < 4; i++)
#pragma unroll
        for (int j = 0; j < 4; j++)
#pragma unroll
            for (int q = 0; q < 4; q++) acc[i][j][q] = 0.f;

    auto load_stage = [&](int s, int kt) {
        const uint32_t Asm = sb + s * BSTG;
        const uint32_t Bsm = Asm + 128 * BROWB;
        const int k0 = kt * BKC;
#pragma unroll
        for (int c4 = 0; c4 < 4; c4++) {
            const int c = tid + c4 * 256;
            const int row = c >> 3, kq = c & 7;
            const int m = bm + row;
            const __nv_bfloat16* src =
                A + (size_t)(m < M ? m : M - 1) * KDIM + k0 + kq * 8;
            const uint32_t dst = Asm + row * BROWB + kq * 16;
            const int sz = (m < M) ? 16 : 0;
            asm volatile("cp.async.cg.shared.global [%0], [%1], 16, %2;"
                         :: "r"(dst), "l"(src), "r"(sz) : "memory");
        }
#pragma unroll
        for (int c4 = 0; c4 < 4; c4++) {
            const int c = tid + c4 * 256;
            const int row = c >> 3, kq = c & 7;
            const __nv_bfloat16* src =
                B + (size_t)(bn + row) * KDIM + k0 + kq * 8;
            const uint32_t dst = Bsm + row * BROWB + kq * 16;
            asm volatile("cp.async.cg.shared.global [%0], [%1], 16, 16;"
                         :: "r"(dst), "l"(src) : "memory");
        }
    };

#pragma unroll
    for (int s = 0; s < NSTG - 1; s++) {
        load_stage(s, s);
        asm volatile("cp.async.commit_group;" ::: "memory");
    }

    int sc_ = 0;
    for (int kt = 0; kt < BNKT; kt++) {
        asm volatile("cp.async.wait_group %0;" :: "n"(NSTG - 2) : "memory");
        __syncthreads();
        if (kt + NSTG - 1 < BNKT) {
            int ns = sc_ + 2; if (ns >= NSTG) ns -= NSTG;
            load_stage(ns, kt + NSTG - 1);
        }
        asm volatile("cp.async.commit_group;" ::: "memory");

        const uint32_t Asm = sb + sc_ * BSTG;
        const uint32_t Bsm = Asm + 128 * BROWB;

#pragma unroll
        for (int ks = 0; ks < 4; ks++) {
            const int kb = ks * 32;
            uint32_t af[4][4], bf[4][2];
#pragma unroll
            for (int mt = 0; mt < 4; mt++) {
                const uint32_t a =
                    Asm + (wm + mt * 16 + (lane & 15)) * BROWB + (lane >> 4) * 16 + kb;
                LDSM4(af[mt], a);
            }
#pragma unroll
            for (int p = 0; p < 2; p++) {
                const int t = lane >> 3;
                const int nr = wn + (2 * p + (t >> 1)) * 8 + (lane & 7);
                const uint32_t a = Bsm + nr * BROWB + (t & 1) * 16 + kb;
                uint32_t r[4];
                LDSM4(r, a);
                bf[2 * p][0] = r[0]; bf[2 * p][1] = r[1];
                bf[2 * p + 1][0] = r[2]; bf[2 * p + 1][1] = r[3];
            }
#pragma unroll
            for (int mt = 0; mt < 4; mt++)
#pragma unroll
                for (int nt = 0; nt < 4; nt++)
                    mma_bf16(acc[mt][nt], af[mt], bf[nt][0], bf[nt][1]);
        }
        if (++sc_ >= NSTG) sc_ = 0;
    }

#pragma unroll
    for (int mt = 0; mt < 4; mt++) {
#pragma unroll
        for (int half = 0; half < 2; half++) {
            const int m = bm + wm + mt * 16 + g + half * 8;
            if (m < M) {
#pragma unroll
                for (int nt = 0; nt < 4; nt++) {
                    const int n = bn + wn + nt * 8 + 2 * tk;
                    float vx = acc[mt][nt][half * 2 + 0];
                    float vy = acc[mt][nt][half * 2 + 1];
                    if (EPI) {
                        const float2 bz = *(const float2*)&bias[n];
                        const float2 rz = *(const float2*)&res[(size_t)m * Ng + n];
                        vx += bz.x + rz.x;
                        vy += bz.y + rz.y;
                    }
                    if (sizeof(OutT) == 2) {
                        *(__nv_bfloat162*)&C[(size_t)m * Ng + n] =
                            __floats2bfloat162_rn(vx, vy);
                    } else {
                        float2 v; v.x = vx; v.y = vy;
                        *(float2*)&C[(size_t)m * Ng + n] = v;
                    }
                }
            }
        }
    }
}

// ---------------------------------------------------------------------------
// bf16 mma.sync attention, flash-style 2-chunk online softmax (R11 structure)
// + base-2 softmax (log2e folded into scale) + MUFU reciprocal.
// ---------------------------------------------------------------------------
#define AJP 208
#define AROWB2 144
#define ATT_SMEM (3 * AJP * AROWB2)   // 89856 B

__global__ __launch_bounds__(256, 2)
void attn_bf16(const __nv_bfloat16* __restrict__ qkv,
               const float* __restrict__ scale,
               __nv_bfloat16* __restrict__ attout)
{
    const int bh = blockIdx.x;
    const int b = bh / HEADS;
    const int h = bh % HEADS;
    const float sc2 = scale[h] * 1.44269504f;   // fold log2(e): softmax in base 2

    extern __shared__ char smc[];
    const uint32_t sb = smem_u32(smc);
    const uint32_t Qs = sb;
    const uint32_t Ks = sb + AJP * AROWB2;
    const uint32_t Vs = sb + 2 * AJP * AROWB2;

    const int tid = threadIdx.x;
    const __nv_bfloat16* base = qkv + (size_t)b * SEQ * QKV_N + h * HD;

    for (int c = tid; c < 3 * AJP * 8; c += 256) {
        const int t = c / (AJP * 8);
        const int rc = c % (AJP * 8);
        const int row = rc >> 3, ch = rc & 7;
        const __nv_bfloat16* src =
            base + (size_t)(row < SEQ ? row : SEQ - 1) * QKV_N + t * DIM + ch * 8;
        const uint32_t dst = sb + t * (AJP * AROWB2) + row * AROWB2 + ch * 16;
        const int sz = (row < SEQ) ? 16 : 0;
        asm volatile("cp.async.cg.shared.global [%0], [%1], 16, %2;"
                     :: "r"(dst), "l"(src), "r"(sz) : "memory");
    }
    asm volatile("cp.async.commit_group;" ::: "memory");
    asm volatile("cp.async.wait_group 0;" ::: "memory");
    __syncthreads();

    const int w = tid >> 5;
    const int lane = tid & 31;
    const int g = lane >> 2;
    const int tk = lane & 3;

    for (int rb = 0; rb < 2; rb++) {
        const int rowbase = rb * 128 + w * 16;
        if (rowbase >= SEQ) continue;
        const int rlo = rowbase + g;
        const int rhi = rlo + 8;

        uint32_t qa[4][4];
#pragma unroll
        for (int ks = 0; ks < 4; ks++)
            LDSM4(qa[ks], Qs + (rowbase + (lane & 15)) * AROWB2
                             + (lane >> 4) * 16 + ks * 32);

        float run_mlo = -1e30f, run_mhi = -1e30f;
        float slo = 0.f, shi = 0.f;
        float O[8][4];
#pragma unroll
        for (int dt = 0; dt < 8; dt++)
            O[dt][0] = O[dt][1] = O[dt][2] = O[dt][3] = 0.f;

#pragma unroll
        for (int c = 0; c < 2; c++) {
            const int p0 = (c == 0) ? 0 : 7;
            const int p1 = (c == 0) ? 7 : 13;
            const int NP = p1 - p0;

            float S[7][2][4];
#pragma unroll
            for (int l = 0; l < 7; l++) {
                if (l >= NP) break;
                const int np = p0 + l;
                S[l][0][0] = S[l][0][1] = S[l][0][2] = S[l][0][3] = 0.f;
                S[l][1][0] = S[l][1][1] = S[l][1][2] = S[l][1][3] = 0.f;
#pragma unroll
                for (int ks = 0; ks < 4; ks++) {
                    uint32_t r[4];
                    LDSM4(r, Ks + (np * 16 + (lane & 15)) * AROWB2
                                + (lane >> 4) * 16 + ks * 32);
                    mma_bf16(S[l][0], qa[ks], r[0], r[2]);
                    mma_bf16(S[l][1], qa[ks], r[1], r[3]);
                }
            }

            // scale (base-2) + diagonal / out-of-range mask
#pragma unroll
            for (int l = 0; l < 7; l++) {
                if (l >= NP) break;
#pragma unroll
                for (int hf = 0; hf < 2; hf++) {
                    const int j0 = (2 * (p0 + l) + hf) * 8 + 2 * tk;
                    const int j1 = j0 + 1;
                    S[l][hf][0] = (j0 == rlo || j0 >= SEQ) ? -1e30f : S[l][hf][0] * sc2;
                    S[l][hf][1] = (j1 == rlo || j1 >= SEQ) ? -1e30f : S[l][hf][1] * sc2;
                    S[l][hf][2] = (j0 == rhi || j0 >= SEQ) ? -1e30f : S[l][hf][2] * sc2;
                    S[l][hf][3] = (j1 == rhi || j1 >= SEQ) ? -1e30f : S[l][hf][3] * sc2;
                }
            }

            float cmlo = -1e30f, cmhi = -1e30f;
#pragma unroll
            for (int l = 0; l < 7; l++) {
                if (l >= NP) break;
#pragma unroll
                for (int hf = 0; hf < 2; hf++) {
                    cmlo = fmaxf(cmlo, fmaxf(S[l][hf][0], S[l][hf][1]));
                    cmhi = fmaxf(cmhi, fmaxf(S[l][hf][2], S[l][hf][3]));
                }
            }
            cmlo = fmaxf(cmlo, __shfl_xor_sync(0xffffffffu, cmlo, 1));
            cmlo = fmaxf(cmlo, __shfl_xor_sync(0xffffffffu, cmlo, 2));
            cmhi = fmaxf(cmhi, __shfl_xor_sync(0xffffffffu, cmhi, 1));
            cmhi = fmaxf(cmhi, __shfl_xor_sync(0xffffffffu, cmhi, 2));

            const float nmlo = fmaxf(run_mlo, cmlo);
            const float nmhi = fmaxf(run_mhi, cmhi);
            const float rfl = exp2f(run_mlo - nmlo);
            const float rfh = exp2f(run_mhi - nmhi);
            run_mlo = nmlo; run_mhi = nmhi;
            slo *= rfl; shi *= rfh;
#pragma unroll
            for (int dt = 0; dt < 8; dt++) {
                O[dt][0] *= rfl; O[dt][1] *= rfl;
                O[dt][2] *= rfh; O[dt][3] *= rfh;
            }

#pragma unroll
            for (int l = 0; l < 7; l++) {
                if (l >= NP) break;
#pragma unroll
                for (int hf = 0; hf < 2; hf++) {
                    S[l][hf][0] = exp2f(S[l][hf][0] - nmlo);
                    S[l][hf][1] = exp2f(S[l][hf][1] - nmlo);
                    S[l][hf][2] = exp2f(S[l][hf][2] - nmhi);
                    S[l][hf][3] = exp2f(S[l][hf][3] - nmhi);
                    slo += S[l][hf][0] + S[l][hf][1];
                    shi += S[l][hf][2] + S[l][hf][3];
                }
            }

#pragma unroll
            for (int l = 0; l < 7; l++) {
                if (l >= NP) break;
                uint32_t pa[4];
                pa[0] = pack_bf16(S[l][0][0], S[l][0][1]);
                pa[1] = pack_bf16(S[l][0][2], S[l][0][3]);
                pa[2] = pack_bf16(S[l][1][0], S[l][1][1]);
                pa[3] = pack_bf16(S[l][1][2], S[l][1][3]);
#pragma unroll
                for (int dp = 0; dp < 4; dp++) {
                    uint32_t r[4];
                    LDSM4T(r, Vs + ((p0 + l) * 16 + (lane & 15)) * AROWB2
                                 + (lane >> 4) * 16 + dp * 32);
                    mma_bf16(O[2 * dp],     pa, r[0], r[1]);
                    mma_bf16(O[2 * dp + 1], pa, r[2], r[3]);
                }
            }
        }

        slo += __shfl_xor_sync(0xffffffffu, slo, 1);
        slo += __shfl_xor_sync(0xffffffffu, slo, 2);
        shi += __shfl_xor_sync(0xffffffffu, shi, 1);
        shi += __shfl_xor_sync(0xffffffffu, shi, 2);
        const float inv_lo = __frcp_rn(slo);
        const float inv_hi = __frcp_rn(shi);

        __nv_bfloat16* orow_lo = attout + (size_t)(b * SEQ + rlo) * DIM + h * HD;
        __nv_bfloat16* orow_hi = attout + (size_t)(b * SEQ + rhi) * DIM + h * HD;
#pragma unroll
        for (int dt = 0; dt < 8; dt++) {
            const int d = dt * 8 + 2 * tk;
            if (rlo < SEQ)
                *(__nv_bfloat162*)&orow_lo[d] =
                    __floats2bfloat162_rn(O[dt][0] * inv_lo, O[dt][1] * inv_lo);
            if (rhi < SEQ)
                *(__nv_bfloat162*)&orow_hi[d] =
                    __floats2bfloat162_rn(O[dt][2] * inv_hi, O[dt][3] * inv_hi);
        }
    }
}

// ---------------------------------------------------------------------------
extern "C" void kernel_launch(void* const* d_in, const int* in_sizes, int n_in,
                              void* d_out, int out_size)
{
    const float* x      = (const float*)d_in[0];
    const float* scale  = (const float*)d_in[1];
    const float* w_qkv  = (const float*)d_in[2];
    const float* w_proj = (const float*)d_in[3];
    const float* b_proj = (const float*)d_in[4];
    float* out = (float*)d_out;

    __nv_bfloat16* qkvb;  cudaGetSymbolAddress((void**)&qkvb, g_qkvb);
    __nv_bfloat16* xb;    cudaGetSymbolAddress((void**)&xb, g_xb);
    __nv_bfloat16* wqb;   cudaGetSymbolAddress((void**)&wqb, g_wqb);
    __nv_bfloat16* wpb;   cudaGetSymbolAddress((void**)&wpb, g_wpb);
    __nv_bfloat16* attb;  cudaGetSymbolAddress((void**)&attb, g_attb);

    cudaFuncSetAttribute((const void*)bf16_gemm<false, __nv_bfloat16>,
                         cudaFuncAttributeMaxDynamicSharedMemorySize, BGEMM_SMEM);
    cudaFuncSetAttribute((const void*)bf16_gemm<true, float>,
                         cudaFuncAttributeMaxDynamicSharedMemorySize, BGEMM_SMEM);
    cudaFuncSetAttribute((const void*)attn_bf16,
                         cudaFuncAttributeMaxDynamicSharedMemorySize, ATT_SMEM);

    // 0) fused fp32 -> bf16 conversion
    cvt_all<<<(N4_ALL + 255) / 256, 256>>>(x, w_qkv, w_proj, xb, wqb, wpb);

    // 1) qkv = x @ w_qkv^T  (128x128 tiles)
    dim3 g1((M_TOT + MT - 1) / MT, QKV_N / NTL);
    bf16_gemm<false, __nv_bfloat16><<<g1, 256, BGEMM_SMEM>>>(
        xb, wqb, qkvb, M_TOT, QKV_N, nullptr, nullptr);

    // 2) attention (online-softmax base-2, 2 CTAs/SM)
    attn_bf16<<<BATCH * HEADS, 256, ATT_SMEM>>>(qkvb, scale, attb);

    // 3) out = att @ w_proj^T + b_proj + x  (128x128 tiles, proven fastest)
    dim3 g2((M_TOT + MT - 1) / MT, DIM / NTL);
    bf16_gemm<true, float><<<g2, 256, BGEMM_SMEM>>>(
        attb, wpb, out, M_TOT, DIM, b_proj, x);
}

// round 14
// speedup vs baseline: 1.0485x; 1.0022x over previous
#include <cuda_runtime.h>
#include <cuda_bf16.h>
#include <cstdint>

// Problem constants
#define BATCH 64
#define SEQ   197
#define DIM   768
#define HEADS 12
#define HD    64
#define M_TOT (BATCH * SEQ)      // 12608
#define QKV_N (3 * DIM)          // 2304
#define KDIM  768

// Scratch (bf16 end-to-end between GEMMs)
__device__ __nv_bfloat16 g_qkvb[(size_t)M_TOT * QKV_N];
__device__ __nv_bfloat16 g_xb[(size_t)M_TOT * DIM];
__device__ __nv_bfloat16 g_wqb[(size_t)QKV_N * KDIM];
__device__ __nv_bfloat16 g_wpb[(size_t)DIM * KDIM];
__device__ __nv_bfloat16 g_attb[(size_t)M_TOT * DIM];

__device__ __forceinline__ uint32_t smem_u32(const void* p) {
    uint32_t a;
    asm("{ .reg .u64 t; cvta.to.shared.u64 t, %1; cvt.u32.u64 %0, t; }" : "=r"(a) : "l"(p));
    return a;
}

__device__ __forceinline__ void mma_bf16(float* c, const uint32_t* a,
                                         uint32_t b0, uint32_t b1) {
    asm volatile(
        "mma.sync.aligned.m16n8k16.row.col.f32.bf16.bf16.f32 "
        "{%0,%1,%2,%3}, {%4,%5,%6,%7}, {%8,%9}, {%0,%1,%2,%3};"
        : "+f"(c[0]), "+f"(c[1]), "+f"(c[2]), "+f"(c[3])
        : "r"(a[0]), "r"(a[1]), "r"(a[2]), "r"(a[3]), "r"(b0), "r"(b1));
}

#define LDSM4(r, addr) \
    asm volatile("ldmatrix.sync.aligned.m8n8.x4.shared.b16 {%0,%1,%2,%3}, [%4];" \
                 : "=r"((r)[0]), "=r"((r)[1]), "=r"((r)[2]), "=r"((r)[3]) : "r"(addr))
#define LDSM4T(r, addr) \
    asm volatile("ldmatrix.sync.aligned.m8n8.x4.trans.shared.b16 {%0,%1,%2,%3}, [%4];" \
                 : "=r"((r)[0]), "=r"((r)[1]), "=r"((r)[2]), "=r"((r)[3]) : "r"(addr))

__device__ __forceinline__ uint32_t pack_bf16(float lo, float hi) {
    __nv_bfloat162 v = __floats2bfloat162_rn(lo, hi);
    return *(uint32_t*)&v;
}

// ---------------------------------------------------------------------------
// fused fp32 -> bf16 conversion for x, w_qkv, w_proj (single launch)
// ---------------------------------------------------------------------------
#define N4_X   ((M_TOT * DIM) / 4)
#define N4_WQ  ((QKV_N * KDIM) / 4)
#define N4_WP  ((DIM * KDIM) / 4)
#define N4_ALL (N4_X + N4_WQ + N4_WP)

__global__ void cvt_all(const float* __restrict__ x,
                        const float* __restrict__ wq,
                        const float* __restrict__ wp,
                        __nv_bfloat16* __restrict__ xb,
                        __nv_bfloat16* __restrict__ wqb,
                        __nv_bfloat16* __restrict__ wpb)
{
    int i = blockIdx.x * blockDim.x + threadIdx.x;
    const float* in;
    __nv_bfloat16* out;
    if (i < N4_X) { in = x; out = xb; }
    else if (i < N4_X + N4_WQ) { i -= N4_X; in = wq; out = wqb; }
    else if (i < N4_ALL) { i -= N4_X + N4_WQ; in = wp; out = wpb; }
    else return;
    const float4 v = ((const float4*)in)[i];
    ((__nv_bfloat162*)out)[2 * i]     = __floats2bfloat162_rn(v.x, v.y);
    ((__nv_bfloat162*)out)[2 * i + 1] = __floats2bfloat162_rn(v.z, v.w);
}

// ---------------------------------------------------------------------------
// bf16 mma.sync GEMM (NT), CTA 128x128, warp 64x32, K-chunk 64, 3 stages.
// (R9/R11/R13 version — best measured)
// ---------------------------------------------------------------------------
#define MT 128
#define NTL 128
#define BKC 64
#define BNKT (KDIM / BKC)          // 12
#define BROWB 144
#define BSTG (256 * BROWB)         // 36864 B per stage
#define NSTG 3
#define BGEMM_SMEM (NSTG * BSTG)   // 110592 B (x2 CTAs = 221184 <= 228K)

template <bool EPI, typename OutT>
__global__ __launch_bounds__(256, 2)
void bf16_gemm(const __nv_bfloat16* __restrict__ A,
               const __nv_bfloat16* __restrict__ B,
               OutT* __restrict__ C, int M, int Ng,
               const float* __restrict__ bias, const float* __restrict__ res)
{
    extern __shared__ char smc[];
    const uint32_t sb = smem_u32(smc);

    const int tid = threadIdx.x;
    const int bm = blockIdx.x * MT;
    const int bn = blockIdx.y * NTL;

    const int w = tid >> 5, lane = tid & 31;
    const int wm = (w & 1) * 64;
    const int wn = (w >> 1) * 32;
    const int g = lane >> 2;
    const int tk = lane & 3;

    float acc[4][4][4];
#pragma unroll
    for (int i = 0; i < 4; i++)
#pragma unroll
        for (int j = 0; j < 4; j++)
#pragma unroll
            for (int q = 0; q < 4; q++) acc[i][j][q] = 0.f;

    auto load_stage = [&](int s, int kt) {
        const uint32_t Asm = sb + s * BSTG;
        const uint32_t Bsm = Asm + 128 * BROWB;
        const int k0 = kt * BKC;
#pragma unroll
        for (int c4 = 0; c4 < 4; c4++) {
            const int c = tid + c4 * 256;
            const int row = c >> 3, kq = c & 7;
            const int m = bm + row;
            const __nv_bfloat16* src =
                A + (size_t)(m < M ? m : M - 1) * KDIM + k0 + kq * 8;
            const uint32_t dst = Asm + row * BROWB + kq * 16;
            const int sz = (m < M) ? 16 : 0;
            asm volatile("cp.async.cg.shared.global [%0], [%1], 16, %2;"
                         :: "r"(dst), "l"(src), "r"(sz) : "memory");
        }
#pragma unroll
        for (int c4 = 0; c4 < 4; c4++) {
            const int c = tid + c4 * 256;
            const int row = c >> 3, kq = c & 7;
            const __nv_bfloat16* src =
                B + (size_t)(bn + row) * KDIM + k0 + kq * 8;
            const uint32_t dst = Bsm + row * BROWB + kq * 16;
            asm volatile("cp.async.cg.shared.global [%0], [%1], 16, 16;"
                         :: "r"(dst), "l"(src) : "memory");
        }
    };

#pragma unroll
    for (int s = 0; s < NSTG - 1; s++) {
        load_stage(s, s);
        asm volatile("cp.async.commit_group;" ::: "memory");
    }

    int sc_ = 0;
    for (int kt = 0; kt < BNKT; kt++) {
        asm volatile("cp.async.wait_group %0;" :: "n"(NSTG - 2) : "memory");
        __syncthreads();
        if (kt + NSTG - 1 < BNKT) {
            int ns = sc_ + 2; if (ns >= NSTG) ns -= NSTG;
            load_stage(ns, kt + NSTG - 1);
        }
        asm volatile("cp.async.commit_group;" ::: "memory");

        const uint32_t Asm = sb + sc_ * BSTG;
        const uint32_t Bsm = Asm + 128 * BROWB;

#pragma unroll
        for (int ks = 0; ks < 4; ks++) {
            const int kb = ks * 32;
            uint32_t af[4][4], bf[4][2];
#pragma unroll
            for (int mt = 0; mt < 4; mt++) {
                const uint32_t a =
                    Asm + (wm + mt * 16 + (lane & 15)) * BROWB + (lane >> 4) * 16 + kb;
                LDSM4(af[mt], a);
            }
#pragma unroll
            for (int p = 0; p < 2; p++) {
                const int t = lane >> 3;
                const int nr = wn + (2 * p + (t >> 1)) * 8 + (lane & 7);
                const uint32_t a = Bsm + nr * BROWB + (t & 1) * 16 + kb;
                uint32_t r[4];
                LDSM4(r, a);
                bf[2 * p][0] = r[0]; bf[2 * p][1] = r[1];
                bf[2 * p + 1][0] = r[2]; bf[2 * p + 1][1] = r[3];
            }
#pragma unroll
            for (int mt = 0; mt < 4; mt++)
#pragma unroll
                for (int nt = 0; nt < 4; nt++)
                    mma_bf16(acc[mt][nt], af[mt], bf[nt][0], bf[nt][1]);
        }
        if (++sc_ >= NSTG) sc_ = 0;
    }

#pragma unroll
    for (int mt = 0; mt < 4; mt++) {
#pragma unroll
        for (int half = 0; half < 2; half++) {
            const int m = bm + wm + mt * 16 + g + half * 8;
            if (m < M) {
#pragma unroll
                for (int nt = 0; nt < 4; nt++) {
                    const int n = bn + wn + nt * 8 + 2 * tk;
                    float vx = acc[mt][nt][half * 2 + 0];
                    float vy = acc[mt][nt][half * 2 + 1];
                    if (EPI) {
                        const float2 bz = *(const float2*)&bias[n];
                        const float2 rz = *(const float2*)&res[(size_t)m * Ng + n];
                        vx += bz.x + rz.x;
                        vy += bz.y + rz.y;
                    }
                    if (sizeof(OutT) == 2) {
                        *(__nv_bfloat162*)&C[(size_t)m * Ng + n] =
                            __floats2bfloat162_rn(vx, vy);
                    } else {
                        float2 v; v.x = vx; v.y = vy;
                        *(float2*)&C[(size_t)m * Ng + n] = v;
                    }
                }
            }
        }
    }
}

// ---------------------------------------------------------------------------
// bf16 mma.sync attention, flash-style 2-chunk online softmax, base-2.
// 224 threads (7 warps): 13 active warp-tiles of 14 slots (93% vs 81% @ 8w).
// ---------------------------------------------------------------------------
#define AJP 208
#define AROWB2 144
#define ATT_SMEM (3 * AJP * AROWB2)   // 89856 B
#define ATT_THREADS 224

__global__ __launch_bounds__(ATT_THREADS, 2)
void attn_bf16(const __nv_bfloat16* __restrict__ qkv,
               const float* __restrict__ scale,
               __nv_bfloat16* __restrict__ attout)
{
    const int bh = blockIdx.x;
    const int b = bh / HEADS;
    const int h = bh % HEADS;
    const float sc2 = scale[h] * 1.44269504f;   // fold log2(e): base-2 softmax

    extern __shared__ char smc[];
    const uint32_t sb = smem_u32(smc);
    const uint32_t Qs = sb;
    const uint32_t Ks = sb + AJP * AROWB2;
    const uint32_t Vs = sb + 2 * AJP * AROWB2;

    const int tid = threadIdx.x;
    const __nv_bfloat16* base = qkv + (size_t)b * SEQ * QKV_N + h * HD;

    for (int c = tid; c < 3 * AJP * 8; c += ATT_THREADS) {
        const int t = c / (AJP * 8);
        const int rc = c % (AJP * 8);
        const int row = rc >> 3, ch = rc & 7;
        const __nv_bfloat16* src =
            base + (size_t)(row < SEQ ? row : SEQ - 1) * QKV_N + t * DIM + ch * 8;
        const uint32_t dst = sb + t * (AJP * AROWB2) + row * AROWB2 + ch * 16;
        const int sz = (row < SEQ) ? 16 : 0;
        asm volatile("cp.async.cg.shared.global [%0], [%1], 16, %2;"
                     :: "r"(dst), "l"(src), "r"(sz) : "memory");
    }
    asm volatile("cp.async.commit_group;" ::: "memory");
    asm volatile("cp.async.wait_group 0;" ::: "memory");
    __syncthreads();

    const int w = tid >> 5;
    const int lane = tid & 31;
    const int g = lane >> 2;
    const int tk = lane & 3;

    for (int rb = 0; rb < 2; rb++) {
        const int rowbase = rb * 112 + w * 16;   // 7 warps: tiles 0-6, 7-13
        if (rowbase >= SEQ) continue;            // tile 13 (rows 208+) skipped
        const int rlo = rowbase + g;
        const int rhi = rlo + 8;

        uint32_t qa[4][4];
#pragma unroll
        for (int ks = 0; ks < 4; ks++)
            LDSM4(qa[ks], Qs + (rowbase + (lane & 15)) * AROWB2
                             + (lane >> 4) * 16 + ks * 32);

        float run_mlo = -1e30f, run_mhi = -1e30f;
        float slo = 0.f, shi = 0.f;
        float O[8][4];
#pragma unroll
        for (int dt = 0; dt < 8; dt++)
            O[dt][0] = O[dt][1] = O[dt][2] = O[dt][3] = 0.f;

#pragma unroll
        for (int c = 0; c < 2; c++) {
            const int p0 = (c == 0) ? 0 : 7;
            const int p1 = (c == 0) ? 7 : 13;
            const int NP = p1 - p0;

            float S[7][2][4];
#pragma unroll
            for (int l = 0; l < 7; l++) {
                if (l >= NP) break;
                const int np = p0 + l;
                S[l][0][0] = S[l][0][1] = S[l][0][2] = S[l][0][3] = 0.f;
                S[l][1][0] = S[l][1][1] = S[l][1][2] = S[l][1][3] = 0.f;
#pragma unroll
                for (int ks = 0; ks < 4; ks++) {
                    uint32_t r[4];
                    LDSM4(r, Ks + (np * 16 + (lane & 15)) * AROWB2
                                + (lane >> 4) * 16 + ks * 32);
                    mma_bf16(S[l][0], qa[ks], r[0], r[2]);
                    mma_bf16(S[l][1], qa[ks], r[1], r[3]);
                }
            }

            // scale (base-2) + diagonal / out-of-range mask
#pragma unroll
            for (int l = 0; l < 7; l++) {
                if (l >= NP) break;
#pragma unroll
                for (int hf = 0; hf < 2; hf++) {
                    const int j0 = (2 * (p0 + l) + hf) * 8 + 2 * tk;
                    const int j1 = j0 + 1;
                    S[l][hf][0] = (j0 == rlo || j0 >= SEQ) ? -1e30f : S[l][hf][0] * sc2;
                    S[l][hf][1] = (j1 == rlo || j1 >= SEQ) ? -1e30f : S[l][hf][1] * sc2;
                    S[l][hf][2] = (j0 == rhi || j0 >= SEQ) ? -1e30f : S[l][hf][2] * sc2;
                    S[l][hf][3] = (j1 == rhi || j1 >= SEQ) ? -1e30f : S[l][hf][3] * sc2;
                }
            }

            float cmlo = -1e30f, cmhi = -1e30f;
#pragma unroll
            for (int l = 0; l < 7; l++) {
                if (l >= NP) break;
#pragma unroll
                for (int hf = 0; hf < 2; hf++) {
                    cmlo = fmaxf(cmlo, fmaxf(S[l][hf][0], S[l][hf][1]));
                    cmhi = fmaxf(cmhi, fmaxf(S[l][hf][2], S[l][hf][3]));
                }
            }
            cmlo = fmaxf(cmlo, __shfl_xor_sync(0xffffffffu, cmlo, 1));
            cmlo = fmaxf(cmlo, __shfl_xor_sync(0xffffffffu, cmlo, 2));
            cmhi = fmaxf(cmhi, __shfl_xor_sync(0xffffffffu, cmhi, 1));
            cmhi = fmaxf(cmhi, __shfl_xor_sync(0xffffffffu, cmhi, 2));

            const float nmlo = fmaxf(run_mlo, cmlo);
            const float nmhi = fmaxf(run_mhi, cmhi);
            const float rfl = exp2f(run_mlo - nmlo);
            const float rfh = exp2f(run_mhi - nmhi);
            run_mlo = nmlo; run_mhi = nmhi;
            slo *= rfl; shi *= rfh;
#pragma unroll
            for (int dt = 0; dt < 8; dt++) {
                O[dt][0] *= rfl; O[dt][1] *= rfl;
                O[dt][2] *= rfh; O[dt][3] *= rfh;
            }

#pragma unroll
            for (int l = 0; l < 7; l++) {
                if (l >= NP) break;
#pragma unroll
                for (int hf = 0; hf < 2; hf++) {
                    S[l][hf][0] = exp2f(S[l][hf][0] - nmlo);
                    S[l][hf][1] = exp2f(S[l][hf][1] - nmlo);
                    S[l][hf][2] = exp2f(S[l][hf][2] - nmhi);
                    S[l][hf][3] = exp2f(S[l][hf][3] - nmhi);
                    slo += S[l][hf][0] + S[l][hf][1];
                    shi += S[l][hf][2] + S[l][hf][3];
                }
            }

#pragma unroll
            for (int l = 0; l < 7; l++) {
                if (l >= NP) break;
                uint32_t pa[4];
                pa[0] = pack_bf16(S[l][0][0], S[l][0][1]);
                pa[1] = pack_bf16(S[l][0][2], S[l][0][3]);
                pa[2] = pack_bf16(S[l][1][0], S[l][1][1]);
                pa[3] = pack_bf16(S[l][1][2], S[l][1][3]);
#pragma unroll
                for (int dp = 0; dp < 4; dp++) {
                    uint32_t r[4];
                    LDSM4T(r, Vs + ((p0 + l) * 16 + (lane & 15)) * AROWB2
                                 + (lane >> 4) * 16 + dp * 32);
                    mma_bf16(O[2 * dp],     pa, r[0], r[1]);
                    mma_bf16(O[2 * dp + 1], pa, r[2], r[3]);
                }
            }
        }

        slo += __shfl_xor_sync(0xffffffffu, slo, 1);
        slo += __shfl_xor_sync(0xffffffffu, slo, 2);
        shi += __shfl_xor_sync(0xffffffffu, shi, 1);
        shi += __shfl_xor_sync(0xffffffffu, shi, 2);
        const float inv_lo = __frcp_rn(slo);
        const float inv_hi = __frcp_rn(shi);

        __nv_bfloat16* orow_lo = attout + (size_t)(b * SEQ + rlo) * DIM + h * HD;
        __nv_bfloat16* orow_hi = attout + (size_t)(b * SEQ + rhi) * DIM + h * HD;
#pragma unroll
        for (int dt = 0; dt < 8; dt++) {
            const int d = dt * 8 + 2 * tk;
            if (rlo < SEQ)
                *(__nv_bfloat162*)&orow_lo[d] =
                    __floats2bfloat162_rn(O[dt][0] * inv_lo, O[dt][1] * inv_lo);
            if (rhi < SEQ)
                *(__nv_bfloat162*)&orow_hi[d] =
                    __floats2bfloat162_rn(O[dt][2] * inv_hi, O[dt][3] * inv_hi);
        }
    }
}

// ---------------------------------------------------------------------------
extern "C" void kernel_launch(void* const* d_in, const int* in_sizes, int n_in,
                              void* d_out, int out_size)
{
    const float* x      = (const float*)d_in[0];
    const float* scale  = (const float*)d_in[1];
    const float* w_qkv  = (const float*)d_in[2];
    const float* w_proj = (const float*)d_in[3];
    const float* b_proj = (const float*)d_in[4];
    float* out = (float*)d_out;

    __nv_bfloat16* qkvb;  cudaGetSymbolAddress((void**)&qkvb, g_qkvb);
    __nv_bfloat16* xb;    cudaGetSymbolAddress((void**)&xb, g_xb);
    __nv_bfloat16* wqb;   cudaGetSymbolAddress((void**)&wqb, g_wqb);
    __nv_bfloat16* wpb;   cudaGetSymbolAddress((void**)&wpb, g_wpb);
    __nv_bfloat16* attb;  cudaGetSymbolAddress((void**)&attb, g_attb);

    cudaFuncSetAttribute((const void*)bf16_gemm<false, __nv_bfloat16>,
                         cudaFuncAttributeMaxDynamicSharedMemorySize, BGEMM_SMEM);
    cudaFuncSetAttribute((const void*)bf16_gemm<true, float>,
                         cudaFuncAttributeMaxDynamicSharedMemorySize, BGEMM_SMEM);
    cudaFuncSetAttribute((const void*)attn_bf16,
                         cudaFuncAttributeMaxDynamicSharedMemorySize, ATT_SMEM);

    // 0) fused fp32 -> bf16 conversion
    cvt_all<<<(N4_ALL + 255) / 256, 256>>>(x, w_qkv, w_proj, xb, wqb, wpb);

    // 1) qkv = x @ w_qkv^T  (128x128 tiles)
    dim3 g1((M_TOT + MT - 1) / MT, QKV_N / NTL);
    bf16_gemm<false, __nv_bfloat16><<<g1, 256, BGEMM_SMEM>>>(
        xb, wqb, qkvb, M_TOT, QKV_N, nullptr, nullptr);

    // 2) attention (online-softmax base-2, 7 warps, 2 CTAs/SM)
    attn_bf16<<<BATCH * HEADS, ATT_THREADS, ATT_SMEM>>>(qkvb, scale, attb);

    // 3) out = att @ w_proj^T + b_proj + x  (128x128 tiles)
    dim3 g2((M_TOT + MT - 1) / MT, DIM / NTL);
    bf16_gemm<true, float><<<g2, 256, BGEMM_SMEM>>>(
        attb, wpb, out, M_TOT, DIM, b_proj, x);
}

// round 15
// speedup vs baseline: 1.0826x; 1.0326x over previous
#include <cuda_runtime.h>
#include <cuda_bf16.h>
#include <cstdint>

// Problem constants
#define BATCH 64
#define SEQ   197
#define DIM   768
#define HEADS 12
#define HD    64
#define M_TOT (BATCH * SEQ)      // 12608
#define QKV_N (3 * DIM)          // 2304
#define KDIM  768

// Scratch (bf16 end-to-end between GEMMs)
__device__ __nv_bfloat16 g_qkvb[(size_t)M_TOT * QKV_N];
__device__ __nv_bfloat16 g_xb[(size_t)M_TOT * DIM];
__device__ __nv_bfloat16 g_wqb[(size_t)QKV_N * KDIM];
__device__ __nv_bfloat16 g_wpb[(size_t)DIM * KDIM];
__device__ __nv_bfloat16 g_attb[(size_t)M_TOT * DIM];

__device__ __forceinline__ uint32_t smem_u32(const void* p) {
    uint32_t a;
    asm("{ .reg .u64 t; cvta.to.shared.u64 t, %1; cvt.u32.u64 %0, t; }" : "=r"(a) : "l"(p));
    return a;
}

__device__ __forceinline__ void mma_bf16(float* c, const uint32_t* a,
                                         uint32_t b0, uint32_t b1) {
    asm volatile(
        "mma.sync.aligned.m16n8k16.row.col.f32.bf16.bf16.f32 "
        "{%0,%1,%2,%3}, {%4,%5,%6,%7}, {%8,%9}, {%0,%1,%2,%3};"
        : "+f"(c[0]), "+f"(c[1]), "+f"(c[2]), "+f"(c[3])
        : "r"(a[0]), "r"(a[1]), "r"(a[2]), "r"(a[3]), "r"(b0), "r"(b1));
}

#define LDSM4(r, addr) \
    asm volatile("ldmatrix.sync.aligned.m8n8.x4.shared.b16 {%0,%1,%2,%3}, [%4];" \
                 : "=r"((r)[0]), "=r"((r)[1]), "=r"((r)[2]), "=r"((r)[3]) : "r"(addr))
#define LDSM4T(r, addr) \
    asm volatile("ldmatrix.sync.aligned.m8n8.x4.trans.shared.b16 {%0,%1,%2,%3}, [%4];" \
                 : "=r"((r)[0]), "=r"((r)[1]), "=r"((r)[2]), "=r"((r)[3]) : "r"(addr))

__device__ __forceinline__ uint32_t pack_bf16(float lo, float hi) {
    __nv_bfloat162 v = __floats2bfloat162_rn(lo, hi);
    return *(uint32_t*)&v;
}

// ---------------------------------------------------------------------------
// fused fp32 -> bf16 conversion for x, w_qkv, w_proj (single launch)
// ---------------------------------------------------------------------------
#define N4_X   ((M_TOT * DIM) / 4)
#define N4_WQ  ((QKV_N * KDIM) / 4)
#define N4_WP  ((DIM * KDIM) / 4)
#define N4_ALL (N4_X + N4_WQ + N4_WP)

__global__ void cvt_all(const float* __restrict__ x,
                        const float* __restrict__ wq,
                        const float* __restrict__ wp,
                        __nv_bfloat16* __restrict__ xb,
                        __nv_bfloat16* __restrict__ wqb,
                        __nv_bfloat16* __restrict__ wpb)
{
    int i = blockIdx.x * blockDim.x + threadIdx.x;
    const float* in;
    __nv_bfloat16* out;
    if (i < N4_X) { in = x; out = xb; }
    else if (i < N4_X + N4_WQ) { i -= N4_X; in = wq; out = wqb; }
    else if (i < N4_ALL) { i -= N4_X + N4_WQ; in = wp; out = wpb; }
    else return;
    const float4 v = ((const float4*)in)[i];
    ((__nv_bfloat162*)out)[2 * i]     = __floats2bfloat162_rn(v.x, v.y);
    ((__nv_bfloat162*)out)[2 * i + 1] = __floats2bfloat162_rn(v.z, v.w);
}

// ---------------------------------------------------------------------------
// bf16 mma.sync GEMM (NT), CTA 128x128, warp 64x32, K-chunk 64, 3 stages.
// EPI variant: residual tile prefetched into freed stage buffers during the
// last two mainloop iterations; epilogue reads res from smem.
// ---------------------------------------------------------------------------
#define MT 128
#define NTL 128
#define BKC 64
#define BNKT (KDIM / BKC)          // 12
#define BROWB 144
#define BSTG (256 * BROWB)         // 36864 B per stage
#define NSTG 3
#define BGEMM_SMEM (NSTG * BSTG)   // 110592 B (x2 CTAs = 221184 <= 228K)
#define RES_STRIDE 544             // 128 rows x 544 B = 69632 <= 2*BSTG

template <bool EPI, typename OutT>
__global__ __launch_bounds__(256, 2)
void bf16_gemm(const __nv_bfloat16* __restrict__ A,
               const __nv_bfloat16* __restrict__ B,
               OutT* __restrict__ C, int M, int Ng,
               const float* __restrict__ bias, const float* __restrict__ res)
{
    extern __shared__ char smc[];
    const uint32_t sb = smem_u32(smc);

    const int tid = threadIdx.x;
    const int bm = blockIdx.x * MT;
    const int bn = blockIdx.y * NTL;

    const int w = tid >> 5, lane = tid & 31;
    const int wm = (w & 1) * 64;
    const int wn = (w >> 1) * 32;
    const int g = lane >> 2;
    const int tk = lane & 3;

    float acc[4][4][4];
#pragma unroll
    for (int i = 0; i < 4; i++)
#pragma unroll
        for (int j = 0; j < 4; j++)
#pragma unroll
            for (int q = 0; q < 4; q++) acc[i][j][q] = 0.f;

    auto load_stage = [&](int s, int kt) {
        const uint32_t Asm = sb + s * BSTG;
        const uint32_t Bsm = Asm + 128 * BROWB;
        const int k0 = kt * BKC;
#pragma unroll
        for (int c4 = 0; c4 < 4; c4++) {
            const int c = tid + c4 * 256;
            const int row = c >> 3, kq = c & 7;
            const int m = bm + row;
            const __nv_bfloat16* src =
                A + (size_t)(m < M ? m : M - 1) * KDIM + k0 + kq * 8;
            const uint32_t dst = Asm + row * BROWB + kq * 16;
            const int sz = (m < M) ? 16 : 0;
            asm volatile("cp.async.cg.shared.global [%0], [%1], 16, %2;"
                         :: "r"(dst), "l"(src), "r"(sz) : "memory");
        }
#pragma unroll
        for (int c4 = 0; c4 < 4; c4++) {
            const int c = tid + c4 * 256;
            const int row = c >> 3, kq = c & 7;
            const __nv_bfloat16* src =
                B + (size_t)(bn + row) * KDIM + k0 + kq * 8;
            const uint32_t dst = Bsm + row * BROWB + kq * 16;
            asm volatile("cp.async.cg.shared.global [%0], [%1], 16, 16;"
                         :: "r"(dst), "l"(src) : "memory");
        }
    };

#pragma unroll
    for (int s = 0; s < NSTG - 1; s++) {
        load_stage(s, s);
        asm volatile("cp.async.commit_group;" ::: "memory");
    }

    int sc_ = 0;
    for (int kt = 0; kt < BNKT; kt++) {
        asm volatile("cp.async.wait_group %0;" :: "n"(NSTG - 2) : "memory");
        __syncthreads();
        if (kt + NSTG - 1 < BNKT) {
            int ns = sc_ + 2; if (ns >= NSTG) ns -= NSTG;
            load_stage(ns, kt + NSTG - 1);
        } else if (EPI) {
            // Last two iterations: stage buffers freed at kt-1 (guarded by the
            // barrier above) are idle. Prefetch the 64KB fp32 residual tile
            // into the stage-0/1 region: rows [0,64) at kt=BNKT-2 and
            // [64,128) at kt=BNKT-1 (row stride 544 B).
            const int r0 = (kt == BNKT - 2) ? 0 : 64;
#pragma unroll
            for (int c8 = 0; c8 < 8; c8++) {
                const int c = tid + c8 * 256;       // 2048 chunks of 16 B
                const int row = r0 + (c >> 5);
                const int ch = c & 31;
                const int m = bm + row;
                const float* src =
                    res + (size_t)(m < M ? m : M - 1) * Ng + bn + ch * 4;
                const uint32_t dst = sb + row * RES_STRIDE + ch * 16;
                asm volatile("cp.async.cg.shared.global [%0], [%1], 16, 16;"
                             :: "r"(dst), "l"(src) : "memory");
            }
        }
        asm volatile("cp.async.commit_group;" ::: "memory");

        const uint32_t Asm = sb + sc_ * BSTG;
        const uint32_t Bsm = Asm + 128 * BROWB;

#pragma unroll
        for (int ks = 0; ks < 4; ks++) {
            const int kb = ks * 32;
            uint32_t af[4][4], bf[4][2];
#pragma unroll
            for (int mt = 0; mt < 4; mt++) {
                const uint32_t a =
                    Asm + (wm + mt * 16 + (lane & 15)) * BROWB + (lane >> 4) * 16 + kb;
                LDSM4(af[mt], a);
            }
#pragma unroll
            for (int p = 0; p < 2; p++) {
                const int t = lane >> 3;
                const int nr = wn + (2 * p + (t >> 1)) * 8 + (lane & 7);
                const uint32_t a = Bsm + nr * BROWB + (t & 1) * 16 + kb;
                uint32_t r[4];
                LDSM4(r, a);
                bf[2 * p][0] = r[0]; bf[2 * p][1] = r[1];
                bf[2 * p + 1][0] = r[2]; bf[2 * p + 1][1] = r[3];
            }
#pragma unroll
            for (int mt = 0; mt < 4; mt++)
#pragma unroll
                for (int nt = 0; nt < 4; nt++)
                    mma_bf16(acc[mt][nt], af[mt], bf[nt][0], bf[nt][1]);
        }
        if (++sc_ >= NSTG) sc_ = 0;
    }

    if (EPI) {
        asm volatile("cp.async.wait_group 0;" ::: "memory");
        __syncthreads();   // res tile fully resident in smem
    }

    // epilogue
#pragma unroll
    for (int mt = 0; mt < 4; mt++) {
#pragma unroll
        for (int half = 0; half < 2; half++) {
            const int rloc = wm + mt * 16 + g + half * 8;
            const int m = bm + rloc;
            if (m < M) {
#pragma unroll
                for (int nt = 0; nt < 4; nt++) {
                    const int nloc = wn + nt * 8 + 2 * tk;
                    const int n = bn + nloc;
                    float vx = acc[mt][nt][half * 2 + 0];
                    float vy = acc[mt][nt][half * 2 + 1];
                    if (EPI) {
                        const float2 bz = *(const float2*)&bias[n];
                        const float2 rz =
                            *(const float2*)(smc + rloc * RES_STRIDE + nloc * 4);
                        vx += bz.x + rz.x;
                        vy += bz.y + rz.y;
                    }
                    if (sizeof(OutT) == 2) {
                        *(__nv_bfloat162*)&C[(size_t)m * Ng + n] =
                            __floats2bfloat162_rn(vx, vy);
                    } else {
                        float2 v; v.x = vx; v.y = vy;
                        *(float2*)&C[(size_t)m * Ng + n] = v;
                    }
                }
            }
        }
    }
}

// ---------------------------------------------------------------------------
// bf16 mma.sync attention, flash-style 2-chunk online softmax, base-2.
// 224 threads (7 warps). (R14 version — best measured)
// ---------------------------------------------------------------------------
#define AJP 208
#define AROWB2 144
#define ATT_SMEM (3 * AJP * AROWB2)   // 89856 B
#define ATT_THREADS 224

__global__ __launch_bounds__(ATT_THREADS, 2)
void attn_bf16(const __nv_bfloat16* __restrict__ qkv,
               const float* __restrict__ scale,
               __nv_bfloat16* __restrict__ attout)
{
    const int bh = blockIdx.x;
    const int b = bh / HEADS;
    const int h = bh % HEADS;
    const float sc2 = scale[h] * 1.44269504f;   // base-2 softmax

    extern __shared__ char smc[];
    const uint32_t sb = smem_u32(smc);
    const uint32_t Qs = sb;
    const uint32_t Ks = sb + AJP * AROWB2;
    const uint32_t Vs = sb + 2 * AJP * AROWB2;

    const int tid = threadIdx.x;
    const __nv_bfloat16* base = qkv + (size_t)b * SEQ * QKV_N + h * HD;

    for (int c = tid; c < 3 * AJP * 8; c += ATT_THREADS) {
        const int t = c / (AJP * 8);
        const int rc = c % (AJP * 8);
        const int row = rc >> 3, ch = rc & 7;
        const __nv_bfloat16* src =
            base + (size_t)(row < SEQ ? row : SEQ - 1) * QKV_N + t * DIM + ch * 8;
        const uint32_t dst = sb + t * (AJP * AROWB2) + row * AROWB2 + ch * 16;
        const int sz = (row < SEQ) ? 16 : 0;
        asm volatile("cp.async.cg.shared.global [%0], [%1], 16, %2;"
                     :: "r"(dst), "l"(src), "r"(sz) : "memory");
    }
    asm volatile("cp.async.commit_group;" ::: "memory");
    asm volatile("cp.async.wait_group 0;" ::: "memory");
    __syncthreads();

    const int w = tid >> 5;
    const int lane = tid & 31;
    const int g = lane >> 2;
    const int tk = lane & 3;

    for (int rb = 0; rb < 2; rb++) {
        const int rowbase = rb * 112 + w * 16;   // 7 warps: tiles 0-6, 7-13
        if (rowbase >= SEQ) continue;
        const int rlo = rowbase + g;
        const int rhi = rlo + 8;

        uint32_t qa[4][4];
#pragma unroll
        for (int ks = 0; ks < 4; ks++)
            LDSM4(qa[ks], Qs + (rowbase + (lane & 15)) * AROWB2
                             + (lane >> 4) * 16 + ks * 32);

        float run_mlo = -1e30f, run_mhi = -1e30f;
        float slo = 0.f, shi = 0.f;
        float O[8][4];
#pragma unroll
        for (int dt = 0; dt < 8; dt++)
            O[dt][0] = O[dt][1] = O[dt][2] = O[dt][3] = 0.f;

#pragma unroll
        for (int c = 0; c < 2; c++) {
            const int p0 = (c == 0) ? 0 : 7;
            const int p1 = (c == 0) ? 7 : 13;
            const int NP = p1 - p0;

            float S[7][2][4];
#pragma unroll
            for (int l = 0; l < 7; l++) {
                if (l >= NP) break;
                const int np = p0 + l;
                S[l][0][0] = S[l][0][1] = S[l][0][2] = S[l][0][3] = 0.f;
                S[l][1][0] = S[l][1][1] = S[l][1][2] = S[l][1][3] = 0.f;
#pragma unroll
                for (int ks = 0; ks < 4; ks++) {
                    uint32_t r[4];
                    LDSM4(r, Ks + (np * 16 + (lane & 15)) * AROWB2
                                + (lane >> 4) * 16 + ks * 32);
                    mma_bf16(S[l][0], qa[ks], r[0], r[2]);
                    mma_bf16(S[l][1], qa[ks], r[1], r[3]);
                }
            }

#pragma unroll
            for (int l = 0; l < 7; l++) {
                if (l >= NP) break;
#pragma unroll
                for (int hf = 0; hf < 2; hf++) {
                    const int j0 = (2 * (p0 + l) + hf) * 8 + 2 * tk;
                    const int j1 = j0 + 1;
                    S[l][hf][0] = (j0 == rlo || j0 >= SEQ) ? -1e30f : S[l][hf][0] * sc2;
                    S[l][hf][1] = (j1 == rlo || j1 >= SEQ) ? -1e30f : S[l][hf][1] * sc2;
                    S[l][hf][2] = (j0 == rhi || j0 >= SEQ) ? -1e30f : S[l][hf][2] * sc2;
                    S[l][hf][3] = (j1 == rhi || j1 >= SEQ) ? -1e30f : S[l][hf][3] * sc2;
                }
            }

            float cmlo = -1e30f, cmhi = -1e30f;
#pragma unroll
            for (int l = 0; l < 7; l++) {
                if (l >= NP) break;
#pragma unroll
                for (int hf = 0; hf < 2; hf++) {
                    cmlo = fmaxf(cmlo, fmaxf(S[l][hf][0], S[l][hf][1]));
                    cmhi = fmaxf(cmhi, fmaxf(S[l][hf][2], S[l][hf][3]));
                }
            }
            cmlo = fmaxf(cmlo, __shfl_xor_sync(0xffffffffu, cmlo, 1));
            cmlo = fmaxf(cmlo, __shfl_xor_sync(0xffffffffu, cmlo, 2));
            cmhi = fmaxf(cmhi, __shfl_xor_sync(0xffffffffu, cmhi, 1));
            cmhi = fmaxf(cmhi, __shfl_xor_sync(0xffffffffu, cmhi, 2));

            const float nmlo = fmaxf(run_mlo, cmlo);
            const float nmhi = fmaxf(run_mhi, cmhi);
            const float rfl = exp2f(run_mlo - nmlo);
            const float rfh = exp2f(run_mhi - nmhi);
            run_mlo = nmlo; run_mhi = nmhi;
            slo *= rfl; shi *= rfh;
#pragma unroll
            for (int dt = 0; dt < 8; dt++) {
                O[dt][0] *= rfl; O[dt][1] *= rfl;
                O[dt][2] *= rfh; O[dt][3] *= rfh;
            }

#pragma unroll
            for (int l = 0; l < 7; l++) {
                if (l >= NP) break;
#pragma unroll
                for (int hf = 0; hf < 2; hf++) {
                    S[l][hf][0] = exp2f(S[l][hf][0] - nmlo);
                    S[l][hf][1] = exp2f(S[l][hf][1] - nmlo);
                    S[l][hf][2] = exp2f(S[l][hf][2] - nmhi);
                    S[l][hf][3] = exp2f(S[l][hf][3] - nmhi);
                    slo += S[l][hf][0] + S[l][hf][1];
                    shi += S[l][hf][2] + S[l][hf][3];
                }
            }

#pragma unroll
            for (int l = 0; l < 7; l++) {
                if (l >= NP) break;
                uint32_t pa[4];
                pa[0] = pack_bf16(S[l][0][0], S[l][0][1]);
                pa[1] = pack_bf16(S[l][0][2], S[l][0][3]);
                pa[2] = pack_bf16(S[l][1][0], S[l][1][1]);
                pa[3] = pack_bf16(S[l][1][2], S[l][1][3]);
#pragma unroll
                for (int dp = 0; dp < 4; dp++) {
                    uint32_t r[4];
                    LDSM4T(r, Vs + ((p0 + l) * 16 + (lane & 15)) * AROWB2
                                 + (lane >> 4) * 16 + dp * 32);
                    mma_bf16(O[2 * dp],     pa, r[0], r[1]);
                    mma_bf16(O[2 * dp + 1], pa, r[2], r[3]);
                }
            }
        }

        slo += __shfl_xor_sync(0xffffffffu, slo, 1);
        slo += __shfl_xor_sync(0xffffffffu, slo, 2);
        shi += __shfl_xor_sync(0xffffffffu, shi, 1);
        shi += __shfl_xor_sync(0xffffffffu, shi, 2);
        const float inv_lo = __frcp_rn(slo);
        const float inv_hi = __frcp_rn(shi);

        __nv_bfloat16* orow_lo = attout + (size_t)(b * SEQ + rlo) * DIM + h * HD;
        __nv_bfloat16* orow_hi = attout + (size_t)(b * SEQ + rhi) * DIM + h * HD;
#pragma unroll
        for (int dt = 0; dt < 8; dt++) {
            const int d = dt * 8 + 2 * tk;
            if (rlo < SEQ)
                *(__nv_bfloat162*)&orow_lo[d] =
                    __floats2bfloat162_rn(O[dt][0] * inv_lo, O[dt][1] * inv_lo);
            if (rhi < SEQ)
                *(__nv_bfloat162*)&orow_hi[d] =
                    __floats2bfloat162_rn(O[dt][2] * inv_hi, O[dt][3] * inv_hi);
        }
    }
}

// ---------------------------------------------------------------------------
extern "C" void kernel_launch(void* const* d_in, const int* in_sizes, int n_in,
                              void* d_out, int out_size)
{
    const float* x      = (const float*)d_in[0];
    const float* scale  = (const float*)d_in[1];
    const float* w_qkv  = (const float*)d_in[2];
    const float* w_proj = (const float*)d_in[3];
    const float* b_proj = (const float*)d_in[4];
    float* out = (float*)d_out;

    __nv_bfloat16* qkvb;  cudaGetSymbolAddress((void**)&qkvb, g_qkvb);
    __nv_bfloat16* xb;    cudaGetSymbolAddress((void**)&xb, g_xb);
    __nv_bfloat16* wqb;   cudaGetSymbolAddress((void**)&wqb, g_wqb);
    __nv_bfloat16* wpb;   cudaGetSymbolAddress((void**)&wpb, g_wpb);
    __nv_bfloat16* attb;  cudaGetSymbolAddress((void**)&attb, g_attb);

    cudaFuncSetAttribute((const void*)bf16_gemm<false, __nv_bfloat16>,
                         cudaFuncAttributeMaxDynamicSharedMemorySize, BGEMM_SMEM);
    cudaFuncSetAttribute((const void*)bf16_gemm<true, float>,
                         cudaFuncAttributeMaxDynamicSharedMemorySize, BGEMM_SMEM);
    cudaFuncSetAttribute((const void*)attn_bf16,
                         cudaFuncAttributeMaxDynamicSharedMemorySize, ATT_SMEM);

    // 0) fused fp32 -> bf16 conversion
    cvt_all<<<(N4_ALL + 255) / 256, 256>>>(x, w_qkv, w_proj, xb, wqb, wpb);

    // 1) qkv = x @ w_qkv^T  (128x128 tiles)
    dim3 g1((M_TOT + MT - 1) / MT, QKV_N / NTL);
    bf16_gemm<false, __nv_bfloat16><<<g1, 256, BGEMM_SMEM>>>(
        xb, wqb, qkvb, M_TOT, QKV_N, nullptr, nullptr);

    // 2) attention (online-softmax base-2, 7 warps, 2 CTAs/SM)
    attn_bf16<<<BATCH * HEADS, ATT_THREADS, ATT_SMEM>>>(qkvb, scale, attb);

    // 3) out = att @ w_proj^T + b_proj + x  (128x128 tiles, res prefetched)
    dim3 g2((M_TOT + MT - 1) / MT, DIM / NTL);
    bf16_gemm<true, float><<<g2, 256, BGEMM_SMEM>>>(
        attb, wpb, out, M_TOT, DIM, b_proj, x);
}